// round 14
// baseline (speedup 1.0000x reference)
#include <cuda_runtime.h>
#include <cuda_fp16.h>
#include <math.h>
#include <stdint.h>

#define BB 32
#define SS 2048
#define HH 1024

// ---------------- device scratch ----------------
__device__ float  g_qw[BB * HH];
__device__ float  g_scores[BB * SS];
__device__ float  g_spart[4 * BB * SS];          // split-H score partials
__device__ __half g_k16[(size_t)SS * BB * HH];   // key fp16, same (S,B,H) layout
__device__ __half g_uT16[(size_t)HH * HH];       // Ua^T fp16, [n][k]
__device__ float  g_ctx_part[32 * BB * HH];      // context partials (32 s-chunks)

// ---------------- helpers (base-ISA only) ----------------
__device__ __forceinline__ uint32_t smem_u32(const void* p) {
    uint32_t a;
    asm("{ .reg .u64 t; cvta.to.shared.u64 t, %1; cvt.u32.u64 %0, t; }" : "=r"(a) : "l"(p));
    return a;
}
__device__ __forceinline__ void cp16(uint32_t dst, const void* src) {
    asm volatile("cp.async.cg.shared.global [%0], [%1], 16;" :: "r"(dst), "l"(src));
}
__device__ __forceinline__ void cp_commit() { asm volatile("cp.async.commit_group;"); }
__device__ __forceinline__ void ldsm4(uint32_t* r, uint32_t a) {
    asm volatile("ldmatrix.sync.aligned.m8n8.x4.shared.b16 {%0,%1,%2,%3}, [%4];"
                 : "=r"(r[0]), "=r"(r[1]), "=r"(r[2]), "=r"(r[3]) : "r"(a));
}
__device__ __forceinline__ void mma16816(float* c, const uint32_t* a, const uint32_t* b) {
    asm volatile(
        "mma.sync.aligned.m16n8k16.row.col.f32.f16.f16.f32 "
        "{%0,%1,%2,%3}, {%4,%5,%6,%7}, {%8,%9}, {%0,%1,%2,%3};"
        : "+f"(c[0]), "+f"(c[1]), "+f"(c[2]), "+f"(c[3])
        : "r"(a[0]), "r"(a[1]), "r"(a[2]), "r"(a[3]), "r"(b[0]), "r"(b[1]));
}
// two tanh per MUFU op
__device__ __forceinline__ float2 tanh2_fast(float x0, float x1) {
    __half2 h = __floats2half2_rn(x0, x1);
    uint32_t hb = *(uint32_t*)&h, tb;
    asm("tanh.approx.f16x2 %0, %1;" : "=r"(tb) : "r"(hb));
    __half2 t = *(__half2*)&tb;
    return __half22float2(t);
}

// ---------------------------------------------------------------------------
// prep: fused convert_key + convert_ua + qw (independent streams, one launch).
// blocks [0,128): qw; [128,1152): Ua^T fp16; [1152, 66688): key fp16.
// ---------------------------------------------------------------------------
__global__ void prep_kernel(const float4* __restrict__ k4,
                            const float* __restrict__ Ua,
                            const float* __restrict__ q,
                            const float* __restrict__ Wa,
                            const float* __restrict__ Wab,
                            const float* __restrict__ Uab) {
    __shared__ float sbuf[1056];
    const int j = blockIdx.x, tid = threadIdx.x;

    if (j < 128) {
        const int b = j >> 2;
        const int h = (j & 3) * 256 + tid;
        for (int i = tid; i < HH; i += 256) sbuf[i] = q[b * HH + i];
        __syncthreads();
        float a0 = 0.f, a1 = 0.f, a2 = 0.f, a3 = 0.f;
#pragma unroll 4
        for (int k = 0; k < HH; k += 4) {
            a0 += sbuf[k + 0] * Wa[(size_t)(k + 0) * HH + h];
            a1 += sbuf[k + 1] * Wa[(size_t)(k + 1) * HH + h];
            a2 += sbuf[k + 2] * Wa[(size_t)(k + 2) * HH + h];
            a3 += sbuf[k + 3] * Wa[(size_t)(k + 3) * HH + h];
        }
        g_qw[b * HH + h] = (a0 + a1) + (a2 + a3) + Wab[h] + Uab[h];
    } else if (j < 1152) {
        const int jj = j - 128;
        const int k0 = (jj & 31) * 32, n0 = (jj >> 5) * 32;
        const int tx = tid & 31, ty = tid >> 5;  // (32, 8)
        float (*tile)[33] = (float(*)[33])sbuf;
#pragma unroll
        for (int r = 0; r < 4; r++)
            tile[ty + r * 8][tx] = Ua[(size_t)(k0 + ty + r * 8) * HH + n0 + tx];
        __syncthreads();
#pragma unroll
        for (int r = 0; r < 4; r++)
            g_uT16[(size_t)(n0 + ty + r * 8) * HH + k0 + tx] =
                __float2half(tile[tx][ty + r * 8]);
    } else {
        const size_t i = (size_t)(j - 1152) * 256 + tid;
        const float4 v = k4[i];
        __half2* dst = (__half2*)g_k16;
        dst[i * 2 + 0] = __floats2half2_rn(v.x, v.y);
        dst[i * 2 + 1] = __floats2half2_rn(v.z, v.w);
    }
}

// ---------------------------------------------------------------------------
// scores via mma.sync fp16, SPLIT-H, SLIM TILE for 3 CTAs/SM:
// grid (4, 16, 32), z fastest. CTA z covers h range [z*256, z*256+256) as
// FOUR n-chunks of BN=64 (NTL = 4*16 = 64 k-tiles). CTA tile per pass is
// 128m x 64n -> acc = 32 regs/thread -> ~80 regs -> 3 CTAs/SM (24 warps/SM).
// 8 warps (4m x 2n), warp tile 32x32; 3-stage cp.async (24KB stages).
// ---------------------------------------------------------------------------
#define BM 128
#define BN 64
#define BK 64
#define NTL 64                     // 4 chunks x 16 k-tiles

#define SM_QW   0u                 // 1 KB (256 floats)
#define SM_VA   1024u              // 1 KB
#define SM_RED  2048u              // 1 KB
#define SM_TILE 3072u              // 1024-aligned
#define STAGE_B 24576u             // A 16KB + B 8KB
#define SM_TOT  (SM_TILE + 3u * STAGE_B)   // 76800 B  (x3 CTAs = 230400 <= 228KB)

__global__ void __launch_bounds__(256, 3)
scores_kernel(const float* __restrict__ va) {
    extern __shared__ char sm[];
    const int tid = threadIdx.x, lane = tid & 31, wid = tid >> 5;
    const int wm = wid & 3, wn = wid >> 2;     // warp grid 4(m) x 2(n)
    const int z = blockIdx.x, s0 = blockIdx.y * BM, b = blockIdx.z;
    const uint32_t sb = smem_u32(sm);
    float* s_qw  = (float*)(sm + SM_QW);
    float* s_va  = (float*)(sm + SM_VA);
    float* s_red = (float*)(sm + SM_RED);

    // this CTA's 256-entry h-slice: [z*256, z*256+256)  (4 chunks x BN=64)
    s_qw[tid] = g_qw[b * HH + z * 256 + tid];
    s_va[tid] = va[z * 256 + tid];

    // cp.async per-thread assignments. A: 128 rows x 8 segs (i<4);
    // B: 64 rows x 8 segs (i<2, same formulas since rows<64 there).
    uint32_t a_dst[4];
    const __half* a_src[4];
    uint32_t b_off[2];
#pragma unroll
    for (int i = 0; i < 4; i++) {
        const int c = tid + i * 256, row = c >> 3, seg = c & 7;
        a_dst[i] = (uint32_t)(row * 128 + ((seg ^ (row & 7)) << 4));
        a_src[i] = g_k16 + ((size_t)(s0 + row) * BB + b) * HH + seg * 8;
        if (i < 2) b_off[i] = (uint32_t)(row * HH + seg * 8);
    }

    // ldmatrix per-lane components
    const int arow = wm * 32 + (lane & 15);
    const int aseg = lane >> 4;
    const int brow = wn * 32 + (lane & 7) + ((lane & 16) >> 1);  // warp covers 32 n-rows
    const int bseg = (lane >> 3) & 1;
    const int swz  = lane & 7;

    float rowacc[4] = {0.f, 0.f, 0.f, 0.f};
    float acc[2][4][4];
#pragma unroll
    for (int mf = 0; mf < 2; mf++)
#pragma unroll
        for (int nf = 0; nf < 4; nf++)
#pragma unroll
            for (int j = 0; j < 4; j++) acc[mf][nf][j] = 0.f;

    // tile issuer: tile t (0..63) -> stage t%3; chunk = t>>4, k0 = (t&15)*BK
    auto issue = [&](int t) {
        const int nc = 4 * z + (t >> 4), k0 = (t & 15) * BK;
        const uint32_t st = sb + SM_TILE + (uint32_t)(t % 3) * STAGE_B;
        const __half* uTp = g_uT16 + (size_t)(nc * BN) * HH + k0;
#pragma unroll
        for (int i = 0; i < 4; i++) cp16(st + a_dst[i], a_src[i] + k0);
#pragma unroll
        for (int i = 0; i < 2; i++) cp16(st + 16384u + a_dst[i], uTp + b_off[i]);
        cp_commit();
    };

    issue(0);
    issue(1);

    for (int t = 0; t < NTL; t++) {
        if (t + 1 < NTL) asm volatile("cp.async.wait_group 1;");
        else             asm volatile("cp.async.wait_group 0;");
        __syncthreads();
        if (t + 2 < NTL) issue(t + 2);

        const uint32_t Ab = sb + SM_TILE + (uint32_t)(t % 3) * STAGE_B;
        const uint32_t Bb = Ab + 16384u;

#pragma unroll
        for (int q = 0; q < 4; q++) {
            uint32_t a0[4], a1[4];
            const uint32_t aa = Ab + (uint32_t)(arow * 128 + (((q * 2 + aseg) ^ swz) << 4));
            ldsm4(a0, aa);
            ldsm4(a1, aa + 16 * 128);
            uint32_t breg[2][4];
            const uint32_t ba = Bb + (uint32_t)(brow * 128 + (((q * 2 + bseg) ^ swz) << 4));
#pragma unroll
            for (int u = 0; u < 2; u++) ldsm4(breg[u], ba + (uint32_t)(u * 16 * 128));
#pragma unroll
            for (int mf = 0; mf < 2; mf++) {
                uint32_t* A = mf ? a1 : a0;
#pragma unroll
                for (int nf = 0; nf < 4; nf++)
                    mma16816(acc[mf][nf], A, breg[nf >> 1] + (nf & 1) * 2);
            }
        }

        if ((t & 15) == 15) {
            const int cl = t >> 4;   // chunk 0..3 -> local h base cl*64
#pragma unroll
            for (int mf = 0; mf < 2; mf++)
#pragma unroll
                for (int nf = 0; nf < 4; nf++) {
                    const int h0 = cl * BN + wn * 32 + nf * 8 + (lane & 3) * 2;  // [0,256)
                    const float q0 = s_qw[h0], q1 = s_qw[h0 + 1];
                    const float v0 = s_va[h0], v1 = s_va[h0 + 1];
                    float* c = acc[mf][nf];
                    const float2 t0 = tanh2_fast(c[0] + q0, c[1] + q1);
                    const float2 t1 = tanh2_fast(c[2] + q0, c[3] + q1);
                    rowacc[mf * 2 + 0] += t0.x * v0 + t0.y * v1;
                    rowacc[mf * 2 + 1] += t1.x * v0 + t1.y * v1;
                    c[0] = 0.f; c[1] = 0.f; c[2] = 0.f; c[3] = 0.f;
                }
        }
    }

    // reduce over the 4 col-lanes of each quad
#pragma unroll
    for (int d = 1; d < 4; d <<= 1)
#pragma unroll
        for (int i = 0; i < 4; i++)
            rowacc[i] += __shfl_xor_sync(0xffffffffu, rowacc[i], d);

    if ((lane & 3) == 0) {
        const int r0 = wm * 32 + (lane >> 2);
        s_red[(r0 +  0) * 2 + wn] = rowacc[0];
        s_red[(r0 +  8) * 2 + wn] = rowacc[1];
        s_red[(r0 + 16) * 2 + wn] = rowacc[2];
        s_red[(r0 + 24) * 2 + wn] = rowacc[3];
    }
    __syncthreads();
    if (tid < 128)
        g_spart[(z * BB + b) * SS + s0 + tid] = s_red[tid * 2] + s_red[tid * 2 + 1];
}

// ---------------------------------------------------------------------------
// softmax over S per batch; sums the 4 split-H partials first.
// ---------------------------------------------------------------------------
__global__ void softmax_kernel(float* __restrict__ out) {
    const int b = blockIdx.x, tid = threadIdx.x;
    __shared__ float red[256];
    float local[8];
    float mx = -1e30f;
#pragma unroll
    for (int j = 0; j < 8; j++) {
        const int s = tid + j * 256;
        local[j] = (g_spart[(0 * BB + b) * SS + s] + g_spart[(1 * BB + b) * SS + s])
                 + (g_spart[(2 * BB + b) * SS + s] + g_spart[(3 * BB + b) * SS + s]);
        mx = fmaxf(mx, local[j]);
    }
    red[tid] = mx; __syncthreads();
    for (int off = 128; off > 0; off >>= 1) {
        if (tid < off) red[tid] = fmaxf(red[tid], red[tid + off]);
        __syncthreads();
    }
    const float m = red[0]; __syncthreads();
    float sum = 0.f;
#pragma unroll
    for (int j = 0; j < 8; j++) { local[j] = expf(local[j] - m); sum += local[j]; }
    red[tid] = sum; __syncthreads();
    for (int off = 128; off > 0; off >>= 1) {
        if (tid < off) red[tid] += red[tid + off];
        __syncthreads();
    }
    const float inv = 1.0f / red[0];
#pragma unroll
    for (int j = 0; j < 8; j++) {
        const float w = local[j] * inv;
        const int s = tid + j * 256;
        out[BB * HH + b * SS + s] = w;
        g_scores[b * SS + s] = w;
    }
}

// ---------------------------------------------------------------------------
// context: partials over 32 s-chunks (64 rows each) from fp16 key, then reduce
// ---------------------------------------------------------------------------
__global__ void context_part_kernel() {
    const int b = blockIdx.x, sp = blockIdx.y, tid = threadIdx.x;
    const int s0 = sp * 64;
    __shared__ float ws[64];
    if (tid < 64) ws[tid] = g_scores[b * SS + s0 + tid];
    __syncthreads();
    float4 acc = make_float4(0.f, 0.f, 0.f, 0.f);
    const __half2* kp = (const __half2*)(g_k16 + ((size_t)s0 * BB + b) * HH) + tid * 2;
#pragma unroll 4
    for (int s = 0; s < 64; s++) {
        const float w = ws[s];
        const __half2 v01 = kp[(size_t)s * BB * (HH / 2)];
        const __half2 v23 = kp[(size_t)s * BB * (HH / 2) + 1];
        const float2 f01 = __half22float2(v01);
        const float2 f23 = __half22float2(v23);
        acc.x += w * f01.x; acc.y += w * f01.y; acc.z += w * f23.x; acc.w += w * f23.y;
    }
    ((float4*)g_ctx_part)[((size_t)sp * BB + b) * 256 + tid] = acc;
}

__global__ void ctx_reduce_kernel(float* __restrict__ out) {
    const int t = blockIdx.x * 256 + threadIdx.x;  // 8192 float4 outputs
    float4 acc = make_float4(0.f, 0.f, 0.f, 0.f);
#pragma unroll
    for (int sp = 0; sp < 32; sp++) {
        const float4 v = ((const float4*)g_ctx_part)[(size_t)sp * 8192 + t];
        acc.x += v.x; acc.y += v.y; acc.z += v.z; acc.w += v.w;
    }
    ((float4*)out)[t] = acc;
}

// ---------------------------------------------------------------------------
extern "C" void kernel_launch(void* const* d_in, const int* in_sizes, int n_in,
                              void* d_out, int out_size) {
    (void)in_sizes; (void)n_in; (void)out_size;
    const float* query = (const float*)d_in[0];
    const float* key   = (const float*)d_in[1];
    const float* Wa_w  = (const float*)d_in[2];
    const float* Wa_b  = (const float*)d_in[3];
    const float* Ua_w  = (const float*)d_in[4];
    const float* Ua_b  = (const float*)d_in[5];
    const float* va_w  = (const float*)d_in[6];
    float* out = (float*)d_out;  // [context (B*H) | weights (B*S)]

    cudaFuncSetAttribute(scores_kernel, cudaFuncAttributeMaxDynamicSharedMemorySize, SM_TOT);

    prep_kernel<<<1152 + 65536, 256>>>((const float4*)key, Ua_w, query, Wa_w, Wa_b, Ua_b);
    scores_kernel<<<dim3(4, SS / BM, BB), 256, SM_TOT>>>(va_w);
    softmax_kernel<<<BB, 256>>>(out);
    context_part_kernel<<<dim3(BB, 32), 256>>>();
    ctx_reduce_kernel<<<32, 256>>>(out);
}

// round 16
// speedup vs baseline: 1.0762x; 1.0762x over previous
#include <cuda_runtime.h>
#include <cuda_fp16.h>
#include <math.h>
#include <stdint.h>

#define BB 32
#define SS 2048
#define HH 1024

// ---------------- device scratch ----------------
__device__ float  g_qw[BB * HH];
__device__ float  g_spart[4 * BB * SS];          // split-H score partials
__device__ __half g_k16[(size_t)SS * BB * HH];   // key fp16, same (S,B,H) layout
__device__ __half g_uT16[(size_t)HH * HH];       // Ua^T fp16, [n][k]
__device__ float  g_ctx_part[32 * BB * HH];      // context partials (32 s-chunks)

// ---------------- helpers (base-ISA only) ----------------
__device__ __forceinline__ uint32_t smem_u32(const void* p) {
    uint32_t a;
    asm("{ .reg .u64 t; cvta.to.shared.u64 t, %1; cvt.u32.u64 %0, t; }" : "=r"(a) : "l"(p));
    return a;
}
__device__ __forceinline__ void cp16(uint32_t dst, const void* src) {
    asm volatile("cp.async.cg.shared.global [%0], [%1], 16;" :: "r"(dst), "l"(src));
}
__device__ __forceinline__ void cp_commit() { asm volatile("cp.async.commit_group;"); }
__device__ __forceinline__ void ldsm4(uint32_t* r, uint32_t a) {
    asm volatile("ldmatrix.sync.aligned.m8n8.x4.shared.b16 {%0,%1,%2,%3}, [%4];"
                 : "=r"(r[0]), "=r"(r[1]), "=r"(r[2]), "=r"(r[3]) : "r"(a));
}
__device__ __forceinline__ void mma16816(float* c, const uint32_t* a, const uint32_t* b) {
    asm volatile(
        "mma.sync.aligned.m16n8k16.row.col.f32.f16.f16.f32 "
        "{%0,%1,%2,%3}, {%4,%5,%6,%7}, {%8,%9}, {%0,%1,%2,%3};"
        : "+f"(c[0]), "+f"(c[1]), "+f"(c[2]), "+f"(c[3])
        : "r"(a[0]), "r"(a[1]), "r"(a[2]), "r"(a[3]), "r"(b[0]), "r"(b[1]));
}
// two tanh per MUFU op
__device__ __forceinline__ float2 tanh2_fast(float x0, float x1) {
    __half2 h = __floats2half2_rn(x0, x1);
    uint32_t hb = *(uint32_t*)&h, tb;
    asm("tanh.approx.f16x2 %0, %1;" : "=r"(tb) : "r"(hb));
    __half2 t = *(__half2*)&tb;
    return __half22float2(t);
}

// ---------------------------------------------------------------------------
// prep: fused convert_key + convert_ua + qw (independent streams, one launch).
// blocks [0,128): qw; [128,1152): Ua^T fp16; [1152, 66688): key fp16.
// ---------------------------------------------------------------------------
__global__ void prep_kernel(const float4* __restrict__ k4,
                            const float* __restrict__ Ua,
                            const float* __restrict__ q,
                            const float* __restrict__ Wa,
                            const float* __restrict__ Wab,
                            const float* __restrict__ Uab) {
    __shared__ float sbuf[1056];
    const int j = blockIdx.x, tid = threadIdx.x;

    if (j < 128) {
        const int b = j >> 2;
        const int h = (j & 3) * 256 + tid;
        for (int i = tid; i < HH; i += 256) sbuf[i] = q[b * HH + i];
        __syncthreads();
        float a0 = 0.f, a1 = 0.f, a2 = 0.f, a3 = 0.f;
#pragma unroll 4
        for (int k = 0; k < HH; k += 4) {
            a0 += sbuf[k + 0] * Wa[(size_t)(k + 0) * HH + h];
            a1 += sbuf[k + 1] * Wa[(size_t)(k + 1) * HH + h];
            a2 += sbuf[k + 2] * Wa[(size_t)(k + 2) * HH + h];
            a3 += sbuf[k + 3] * Wa[(size_t)(k + 3) * HH + h];
        }
        g_qw[b * HH + h] = (a0 + a1) + (a2 + a3) + Wab[h] + Uab[h];
    } else if (j < 1152) {
        const int jj = j - 128;
        const int k0 = (jj & 31) * 32, n0 = (jj >> 5) * 32;
        const int tx = tid & 31, ty = tid >> 5;  // (32, 8)
        float (*tile)[33] = (float(*)[33])sbuf;
#pragma unroll
        for (int r = 0; r < 4; r++)
            tile[ty + r * 8][tx] = Ua[(size_t)(k0 + ty + r * 8) * HH + n0 + tx];
        __syncthreads();
#pragma unroll
        for (int r = 0; r < 4; r++)
            g_uT16[(size_t)(n0 + ty + r * 8) * HH + k0 + tx] =
                __float2half(tile[tx][ty + r * 8]);
    } else {
        const size_t i = (size_t)(j - 1152) * 256 + tid;
        const float4 v = k4[i];
        __half2* dst = (__half2*)g_k16;
        dst[i * 2 + 0] = __floats2half2_rn(v.x, v.y);
        dst[i * 2 + 1] = __floats2half2_rn(v.z, v.w);
    }
}

// ---------------------------------------------------------------------------
// scores via mma.sync fp16, SPLIT-H (R13 structure — converged optimum):
// grid (4, 16, 32), z fastest. CTA z covers h range [z*256,+256) as 2 chunks
// of BN=128. BM=128, BK=64; 8 warps (4m x 2n); 3-stage cp.async; 2 CTAs/SM.
// ---------------------------------------------------------------------------
#define BM 128
#define BN 128
#define BK 64
#define NTL 32                     // tiles per CTA: 2 chunks x 16 k-tiles

#define SM_QW   0u                 // 1 KB used (256 floats)
#define SM_VA   4096u              // 1 KB used
#define SM_RED  8192u              // 1 KB
#define SM_TILE 12288u
#define STAGE_B 32768u
#define SM_TOT  (SM_TILE + 3u * STAGE_B)   // 110592 B

__global__ void __launch_bounds__(256, 2)
scores_kernel(const float* __restrict__ va) {
    extern __shared__ char sm[];
    const int tid = threadIdx.x, lane = tid & 31, wid = tid >> 5;
    const int wm = wid & 3, wn = wid >> 2;     // warp grid 4(m) x 2(n)
    const int z = blockIdx.x, s0 = blockIdx.y * BM, b = blockIdx.z;
    const uint32_t sb = smem_u32(sm);
    float* s_qw  = (float*)(sm + SM_QW);
    float* s_va  = (float*)(sm + SM_VA);
    float* s_red = (float*)(sm + SM_RED);

    // this CTA's 256-entry h-slice: [z*256, z*256+256)  (2 chunks x BN=128)
    s_qw[tid] = g_qw[b * HH + z * 256 + tid];
    s_va[tid] = va[z * 256 + tid];

    // cp.async per-thread assignments: 128 rows x 8 segs(16B), XOR swizzle.
    uint32_t a_dst[4];
    const __half* a_src[4];
    uint32_t b_off[4];
#pragma unroll
    for (int i = 0; i < 4; i++) {
        const int c = tid + i * 256, row = c >> 3, seg = c & 7;
        a_dst[i] = (uint32_t)(row * 128 + ((seg ^ (row & 7)) << 4));
        a_src[i] = g_k16 + ((size_t)(s0 + row) * BB + b) * HH + seg * 8;
        b_off[i] = (uint32_t)(row * HH + seg * 8);
    }

    // ldmatrix per-lane components
    const int arow = wm * 32 + (lane & 15);
    const int aseg = lane >> 4;
    const int brow = wn * 64 + (lane & 7) + ((lane & 16) >> 1);
    const int bseg = (lane >> 3) & 1;
    const int swz  = lane & 7;

    float rowacc[4] = {0.f, 0.f, 0.f, 0.f};
    float acc[2][8][4];
#pragma unroll
    for (int mf = 0; mf < 2; mf++)
#pragma unroll
        for (int nf = 0; nf < 8; nf++)
#pragma unroll
            for (int j = 0; j < 4; j++) acc[mf][nf][j] = 0.f;

    // tile issuer: tile t (0..31) -> stage t%3; nc = 2z + (t>>4)
    auto issue = [&](int t) {
        const int nc = 2 * z + (t >> 4), k0 = (t & 15) * BK;
        const uint32_t st = sb + SM_TILE + (uint32_t)(t % 3) * STAGE_B;
        const __half* uTp = g_uT16 + (size_t)(nc * BN) * HH + k0;
#pragma unroll
        for (int i = 0; i < 4; i++) cp16(st + a_dst[i], a_src[i] + k0);
#pragma unroll
        for (int i = 0; i < 4; i++) cp16(st + 16384u + a_dst[i], uTp + b_off[i]);
        cp_commit();
    };

    issue(0);
    issue(1);

    for (int t = 0; t < NTL; t++) {
        if (t + 1 < NTL) asm volatile("cp.async.wait_group 1;");
        else             asm volatile("cp.async.wait_group 0;");
        __syncthreads();
        if (t + 2 < NTL) issue(t + 2);

        const uint32_t Ab = sb + SM_TILE + (uint32_t)(t % 3) * STAGE_B;
        const uint32_t Bb = Ab + 16384u;

#pragma unroll
        for (int q = 0; q < 4; q++) {
            uint32_t a0[4], a1[4];
            const uint32_t aa = Ab + (uint32_t)(arow * 128 + (((q * 2 + aseg) ^ swz) << 4));
            ldsm4(a0, aa);
            ldsm4(a1, aa + 16 * 128);
            uint32_t breg[4][4];
            const uint32_t ba = Bb + (uint32_t)(brow * 128 + (((q * 2 + bseg) ^ swz) << 4));
#pragma unroll
            for (int u = 0; u < 4; u++) ldsm4(breg[u], ba + (uint32_t)(u * 16 * 128));
#pragma unroll
            for (int mf = 0; mf < 2; mf++) {
                uint32_t* A = mf ? a1 : a0;
#pragma unroll
                for (int nf = 0; nf < 8; nf++)
                    mma16816(acc[mf][nf], A, breg[nf >> 1] + (nf & 1) * 2);
            }
        }

        if ((t & 15) == 15) {
            const int cl = t >> 4;   // local chunk 0/1 -> local h base 0/128
#pragma unroll
            for (int mf = 0; mf < 2; mf++)
#pragma unroll
                for (int nf = 0; nf < 8; nf++) {
                    const int h0 = cl * BN + wn * 64 + nf * 8 + (lane & 3) * 2;  // [0,256)
                    const float q0 = s_qw[h0], q1 = s_qw[h0 + 1];
                    const float v0 = s_va[h0], v1 = s_va[h0 + 1];
                    float* c = acc[mf][nf];
                    const float2 t0 = tanh2_fast(c[0] + q0, c[1] + q1);
                    const float2 t1 = tanh2_fast(c[2] + q0, c[3] + q1);
                    rowacc[mf * 2 + 0] += t0.x * v0 + t0.y * v1;
                    rowacc[mf * 2 + 1] += t1.x * v0 + t1.y * v1;
                    c[0] = 0.f; c[1] = 0.f; c[2] = 0.f; c[3] = 0.f;
                }
        }
    }

    // reduce over the 4 col-lanes of each quad
#pragma unroll
    for (int d = 1; d < 4; d <<= 1)
#pragma unroll
        for (int i = 0; i < 4; i++)
            rowacc[i] += __shfl_xor_sync(0xffffffffu, rowacc[i], d);

    if ((lane & 3) == 0) {
        const int r0 = wm * 32 + (lane >> 2);
        s_red[(r0 +  0) * 2 + wn] = rowacc[0];
        s_red[(r0 +  8) * 2 + wn] = rowacc[1];
        s_red[(r0 + 16) * 2 + wn] = rowacc[2];
        s_red[(r0 + 24) * 2 + wn] = rowacc[3];
    }
    __syncthreads();
    if (tid < 128)
        g_spart[(z * BB + b) * SS + s0 + tid] = s_red[tid * 2] + s_red[tid * 2 + 1];
}

// ---------------------------------------------------------------------------
// context_part + FUSED softmax: grid (BB, 32), 256 threads. Every block
// redoes batch-b softmax (bit-identical across blocks -> deterministic),
// keeps weights for its 64 s-rows, and accumulates its context partial.
// Blocks with sp==0 also write the weights output.
// ---------------------------------------------------------------------------
__global__ void context_part_kernel(float* __restrict__ out) {
    const int b = blockIdx.x, sp = blockIdx.y, tid = threadIdx.x;
    const int s0 = sp * 64;
    __shared__ float red[256];
    __shared__ float ws[64];

    // ---- redundant per-batch softmax (reads L2-hot g_spart) ----
    float local[8];
    float mx = -1e30f;
#pragma unroll
    for (int j = 0; j < 8; j++) {
        const int s = tid + j * 256;
        local[j] = (g_spart[(0 * BB + b) * SS + s] + g_spart[(1 * BB + b) * SS + s])
                 + (g_spart[(2 * BB + b) * SS + s] + g_spart[(3 * BB + b) * SS + s]);
        mx = fmaxf(mx, local[j]);
    }
    red[tid] = mx; __syncthreads();
    for (int off = 128; off > 0; off >>= 1) {
        if (tid < off) red[tid] = fmaxf(red[tid], red[tid + off]);
        __syncthreads();
    }
    const float m = red[0]; __syncthreads();
    float sum = 0.f;
#pragma unroll
    for (int j = 0; j < 8; j++) { local[j] = expf(local[j] - m); sum += local[j]; }
    red[tid] = sum; __syncthreads();
    for (int off = 128; off > 0; off >>= 1) {
        if (tid < off) red[tid] += red[tid + off];
        __syncthreads();
    }
    const float inv = 1.0f / red[0];
    __syncthreads();

    // stash this block's 64 weights; sp==0 also writes the weights output
#pragma unroll
    for (int j = 0; j < 8; j++) {
        const int s = tid + j * 256;
        const float w = local[j] * inv;
        if (s >= s0 && s < s0 + 64) ws[s - s0] = w;
        if (sp == 0) out[BB * HH + b * SS + s] = w;
    }
    __syncthreads();

    // ---- context partial over 64 s-rows from fp16 key ----
    float4 acc = make_float4(0.f, 0.f, 0.f, 0.f);
    const __half2* kp = (const __half2*)(g_k16 + ((size_t)s0 * BB + b) * HH) + tid * 2;
#pragma unroll 4
    for (int s = 0; s < 64; s++) {
        const float w = ws[s];
        const __half2 v01 = kp[(size_t)s * BB * (HH / 2)];
        const __half2 v23 = kp[(size_t)s * BB * (HH / 2) + 1];
        const float2 f01 = __half22float2(v01);
        const float2 f23 = __half22float2(v23);
        acc.x += w * f01.x; acc.y += w * f01.y; acc.z += w * f23.x; acc.w += w * f23.y;
    }
    ((float4*)g_ctx_part)[((size_t)sp * BB + b) * 256 + tid] = acc;
}

__global__ void ctx_reduce_kernel(float* __restrict__ out) {
    const int t = blockIdx.x * 256 + threadIdx.x;  // 8192 float4 outputs
    float4 acc = make_float4(0.f, 0.f, 0.f, 0.f);
#pragma unroll
    for (int sp = 0; sp < 32; sp++) {
        const float4 v = ((const float4*)g_ctx_part)[(size_t)sp * 8192 + t];
        acc.x += v.x; acc.y += v.y; acc.z += v.z; acc.w += v.w;
    }
    ((float4*)out)[t] = acc;
}

// ---------------------------------------------------------------------------
extern "C" void kernel_launch(void* const* d_in, const int* in_sizes, int n_in,
                              void* d_out, int out_size) {
    (void)in_sizes; (void)n_in; (void)out_size;
    const float* query = (const float*)d_in[0];
    const float* key   = (const float*)d_in[1];
    const float* Wa_w  = (const float*)d_in[2];
    const float* Wa_b  = (const float*)d_in[3];
    const float* Ua_w  = (const float*)d_in[4];
    const float* Ua_b  = (const float*)d_in[5];
    const float* va_w  = (const float*)d_in[6];
    float* out = (float*)d_out;  // [context (B*H) | weights (B*S)]

    cudaFuncSetAttribute(scores_kernel, cudaFuncAttributeMaxDynamicSharedMemorySize, SM_TOT);

    prep_kernel<<<1152 + 65536, 256>>>((const float4*)key, Ua_w, query, Wa_w, Wa_b, Ua_b);
    scores_kernel<<<dim3(4, SS / BM, BB), 256, SM_TOT>>>(va_w);
    context_part_kernel<<<dim3(BB, 32), 256>>>(out);
    ctx_reduce_kernel<<<32, 256>>>(out);
}

// round 17
// speedup vs baseline: 1.0824x; 1.0058x over previous
#include <cuda_runtime.h>
#include <cuda_fp16.h>
#include <math.h>
#include <stdint.h>

#define BB 32
#define SS 2048
#define HH 1024

// ---------------- device scratch ----------------
__device__ float  g_qw[BB * HH];
__device__ float  g_spart[4 * BB * SS];          // split-H score partials
__device__ __half g_k16[(size_t)SS * BB * HH];   // key fp16, same (S,B,H) layout
__device__ __half g_uT16[(size_t)HH * HH];       // Ua^T fp16, [n][k]
__device__ float  g_ctx_part[32 * BB * HH];      // context partials (32 s-chunks)

// ---------------- helpers (base-ISA only) ----------------
__device__ __forceinline__ uint32_t smem_u32(const void* p) {
    uint32_t a;
    asm("{ .reg .u64 t; cvta.to.shared.u64 t, %1; cvt.u32.u64 %0, t; }" : "=r"(a) : "l"(p));
    return a;
}
__device__ __forceinline__ void cp16(uint32_t dst, const void* src) {
    asm volatile("cp.async.cg.shared.global [%0], [%1], 16;" :: "r"(dst), "l"(src));
}
__device__ __forceinline__ void cp_commit() { asm volatile("cp.async.commit_group;"); }
__device__ __forceinline__ void ldsm4(uint32_t* r, uint32_t a) {
    asm volatile("ldmatrix.sync.aligned.m8n8.x4.shared.b16 {%0,%1,%2,%3}, [%4];"
                 : "=r"(r[0]), "=r"(r[1]), "=r"(r[2]), "=r"(r[3]) : "r"(a));
}
__device__ __forceinline__ void mma16816(float* c, const uint32_t* a, const uint32_t* b) {
    asm volatile(
        "mma.sync.aligned.m16n8k16.row.col.f32.f16.f16.f32 "
        "{%0,%1,%2,%3}, {%4,%5,%6,%7}, {%8,%9}, {%0,%1,%2,%3};"
        : "+f"(c[0]), "+f"(c[1]), "+f"(c[2]), "+f"(c[3])
        : "r"(a[0]), "r"(a[1]), "r"(a[2]), "r"(a[3]), "r"(b[0]), "r"(b[1]));
}
// two tanh per MUFU op
__device__ __forceinline__ float2 tanh2_fast(float x0, float x1) {
    __half2 h = __floats2half2_rn(x0, x1);
    uint32_t hb = *(uint32_t*)&h, tb;
    asm("tanh.approx.f16x2 %0, %1;" : "=r"(tb) : "r"(hb));
    __half2 t = *(__half2*)&tb;
    return __half22float2(t);
}

// ---------------------------------------------------------------------------
// prep: fused convert_key + convert_ua + qw (independent streams, one launch).
// blocks [0,128): qw; [128,1152): Ua^T fp16; [1152, 66688): key fp16.
// ---------------------------------------------------------------------------
__global__ void prep_kernel(const float4* __restrict__ k4,
                            const float* __restrict__ Ua,
                            const float* __restrict__ q,
                            const float* __restrict__ Wa,
                            const float* __restrict__ Wab,
                            const float* __restrict__ Uab) {
    __shared__ float sbuf[1056];
    const int j = blockIdx.x, tid = threadIdx.x;

    if (j < 128) {
        const int b = j >> 2;
        const int h = (j & 3) * 256 + tid;
        for (int i = tid; i < HH; i += 256) sbuf[i] = q[b * HH + i];
        __syncthreads();
        float a0 = 0.f, a1 = 0.f, a2 = 0.f, a3 = 0.f;
#pragma unroll 4
        for (int k = 0; k < HH; k += 4) {
            a0 += sbuf[k + 0] * Wa[(size_t)(k + 0) * HH + h];
            a1 += sbuf[k + 1] * Wa[(size_t)(k + 1) * HH + h];
            a2 += sbuf[k + 2] * Wa[(size_t)(k + 2) * HH + h];
            a3 += sbuf[k + 3] * Wa[(size_t)(k + 3) * HH + h];
        }
        g_qw[b * HH + h] = (a0 + a1) + (a2 + a3) + Wab[h] + Uab[h];
    } else if (j < 1152) {
        const int jj = j - 128;
        const int k0 = (jj & 31) * 32, n0 = (jj >> 5) * 32;
        const int tx = tid & 31, ty = tid >> 5;  // (32, 8)
        float (*tile)[33] = (float(*)[33])sbuf;
#pragma unroll
        for (int r = 0; r < 4; r++)
            tile[ty + r * 8][tx] = Ua[(size_t)(k0 + ty + r * 8) * HH + n0 + tx];
        __syncthreads();
#pragma unroll
        for (int r = 0; r < 4; r++)
            g_uT16[(size_t)(n0 + ty + r * 8) * HH + k0 + tx] =
                __float2half(tile[tx][ty + r * 8]);
    } else {
        const size_t i = (size_t)(j - 1152) * 256 + tid;
        const float4 v = k4[i];
        __half2* dst = (__half2*)g_k16;
        dst[i * 2 + 0] = __floats2half2_rn(v.x, v.y);
        dst[i * 2 + 1] = __floats2half2_rn(v.z, v.w);
    }
}

// ---------------------------------------------------------------------------
// scores via mma.sync fp16, SPLIT-H (converged): grid (4, 16, 32), z fastest.
// CTA z covers h range [z*256,+256) as 2 chunks of BN=128. BM=128, BK=64;
// 8 warps (4m x 2n); 3-stage cp.async; 2 CTAs/SM.
// ---------------------------------------------------------------------------
#define BM 128
#define BN 128
#define BK 64
#define NTL 32                     // tiles per CTA: 2 chunks x 16 k-tiles

#define SM_QW   0u                 // 1 KB used (256 floats)
#define SM_VA   4096u              // 1 KB used
#define SM_RED  8192u              // 1 KB
#define SM_TILE 12288u
#define STAGE_B 32768u
#define SM_TOT  (SM_TILE + 3u * STAGE_B)   // 110592 B

__global__ void __launch_bounds__(256, 2)
scores_kernel(const float* __restrict__ va) {
    extern __shared__ char sm[];
    const int tid = threadIdx.x, lane = tid & 31, wid = tid >> 5;
    const int wm = wid & 3, wn = wid >> 2;     // warp grid 4(m) x 2(n)
    const int z = blockIdx.x, s0 = blockIdx.y * BM, b = blockIdx.z;
    const uint32_t sb = smem_u32(sm);
    float* s_qw  = (float*)(sm + SM_QW);
    float* s_va  = (float*)(sm + SM_VA);
    float* s_red = (float*)(sm + SM_RED);

    // this CTA's 256-entry h-slice: [z*256, z*256+256)  (2 chunks x BN=128)
    s_qw[tid] = g_qw[b * HH + z * 256 + tid];
    s_va[tid] = va[z * 256 + tid];

    // cp.async per-thread assignments: 128 rows x 8 segs(16B), XOR swizzle.
    uint32_t a_dst[4];
    const __half* a_src[4];
    uint32_t b_off[4];
#pragma unroll
    for (int i = 0; i < 4; i++) {
        const int c = tid + i * 256, row = c >> 3, seg = c & 7;
        a_dst[i] = (uint32_t)(row * 128 + ((seg ^ (row & 7)) << 4));
        a_src[i] = g_k16 + ((size_t)(s0 + row) * BB + b) * HH + seg * 8;
        b_off[i] = (uint32_t)(row * HH + seg * 8);
    }

    // ldmatrix per-lane components
    const int arow = wm * 32 + (lane & 15);
    const int aseg = lane >> 4;
    const int brow = wn * 64 + (lane & 7) + ((lane & 16) >> 1);
    const int bseg = (lane >> 3) & 1;
    const int swz  = lane & 7;

    float rowacc[4] = {0.f, 0.f, 0.f, 0.f};
    float acc[2][8][4];
#pragma unroll
    for (int mf = 0; mf < 2; mf++)
#pragma unroll
        for (int nf = 0; nf < 8; nf++)
#pragma unroll
            for (int j = 0; j < 4; j++) acc[mf][nf][j] = 0.f;

    // tile issuer: tile t (0..31) -> stage t%3; nc = 2z + (t>>4)
    auto issue = [&](int t) {
        const int nc = 2 * z + (t >> 4), k0 = (t & 15) * BK;
        const uint32_t st = sb + SM_TILE + (uint32_t)(t % 3) * STAGE_B;
        const __half* uTp = g_uT16 + (size_t)(nc * BN) * HH + k0;
#pragma unroll
        for (int i = 0; i < 4; i++) cp16(st + a_dst[i], a_src[i] + k0);
#pragma unroll
        for (int i = 0; i < 4; i++) cp16(st + 16384u + a_dst[i], uTp + b_off[i]);
        cp_commit();
    };

    issue(0);
    issue(1);

    for (int t = 0; t < NTL; t++) {
        if (t + 1 < NTL) asm volatile("cp.async.wait_group 1;");
        else             asm volatile("cp.async.wait_group 0;");
        __syncthreads();
        if (t + 2 < NTL) issue(t + 2);

        const uint32_t Ab = sb + SM_TILE + (uint32_t)(t % 3) * STAGE_B;
        const uint32_t Bb = Ab + 16384u;

#pragma unroll
        for (int q = 0; q < 4; q++) {
            uint32_t a0[4], a1[4];
            const uint32_t aa = Ab + (uint32_t)(arow * 128 + (((q * 2 + aseg) ^ swz) << 4));
            ldsm4(a0, aa);
            ldsm4(a1, aa + 16 * 128);
            uint32_t breg[4][4];
            const uint32_t ba = Bb + (uint32_t)(brow * 128 + (((q * 2 + bseg) ^ swz) << 4));
#pragma unroll
            for (int u = 0; u < 4; u++) ldsm4(breg[u], ba + (uint32_t)(u * 16 * 128));
#pragma unroll
            for (int mf = 0; mf < 2; mf++) {
                uint32_t* A = mf ? a1 : a0;
#pragma unroll
                for (int nf = 0; nf < 8; nf++)
                    mma16816(acc[mf][nf], A, breg[nf >> 1] + (nf & 1) * 2);
            }
        }

        if ((t & 15) == 15) {
            const int cl = t >> 4;   // local chunk 0/1 -> local h base 0/128
#pragma unroll
            for (int mf = 0; mf < 2; mf++)
#pragma unroll
                for (int nf = 0; nf < 8; nf++) {
                    const int h0 = cl * BN + wn * 64 + nf * 8 + (lane & 3) * 2;  // [0,256)
                    const float q0 = s_qw[h0], q1 = s_qw[h0 + 1];
                    const float v0 = s_va[h0], v1 = s_va[h0 + 1];
                    float* c = acc[mf][nf];
                    const float2 t0 = tanh2_fast(c[0] + q0, c[1] + q1);
                    const float2 t1 = tanh2_fast(c[2] + q0, c[3] + q1);
                    rowacc[mf * 2 + 0] += t0.x * v0 + t0.y * v1;
                    rowacc[mf * 2 + 1] += t1.x * v0 + t1.y * v1;
                    c[0] = 0.f; c[1] = 0.f; c[2] = 0.f; c[3] = 0.f;
                }
        }
    }

    // reduce over the 4 col-lanes of each quad
#pragma unroll
    for (int d = 1; d < 4; d <<= 1)
#pragma unroll
        for (int i = 0; i < 4; i++)
            rowacc[i] += __shfl_xor_sync(0xffffffffu, rowacc[i], d);

    if ((lane & 3) == 0) {
        const int r0 = wm * 32 + (lane >> 2);
        s_red[(r0 +  0) * 2 + wn] = rowacc[0];
        s_red[(r0 +  8) * 2 + wn] = rowacc[1];
        s_red[(r0 + 16) * 2 + wn] = rowacc[2];
        s_red[(r0 + 24) * 2 + wn] = rowacc[3];
    }
    __syncthreads();
    if (tid < 128)
        g_spart[(z * BB + b) * SS + s0 + tid] = s_red[tid * 2] + s_red[tid * 2 + 1];
}

// ---------------------------------------------------------------------------
// context_part + FUSED softmax: grid (BB, 32), 256 threads. Every block
// redoes batch-b softmax (bit-identical across blocks -> deterministic),
// keeps weights for its 64 s-rows, and accumulates its context partial
// with TWO independent float4 chains (double MLP).
// ---------------------------------------------------------------------------
__global__ void context_part_kernel(float* __restrict__ out) {
    const int b = blockIdx.x, sp = blockIdx.y, tid = threadIdx.x;
    const int s0 = sp * 64;
    __shared__ float red[256];
    __shared__ float ws[64];

    // ---- redundant per-batch softmax (reads L2-hot g_spart) ----
    float local[8];
    float mx = -1e30f;
#pragma unroll
    for (int j = 0; j < 8; j++) {
        const int s = tid + j * 256;
        local[j] = (g_spart[(0 * BB + b) * SS + s] + g_spart[(1 * BB + b) * SS + s])
                 + (g_spart[(2 * BB + b) * SS + s] + g_spart[(3 * BB + b) * SS + s]);
        mx = fmaxf(mx, local[j]);
    }
    red[tid] = mx; __syncthreads();
    for (int off = 128; off > 0; off >>= 1) {
        if (tid < off) red[tid] = fmaxf(red[tid], red[tid + off]);
        __syncthreads();
    }
    const float m = red[0]; __syncthreads();
    float sum = 0.f;
#pragma unroll
    for (int j = 0; j < 8; j++) { local[j] = expf(local[j] - m); sum += local[j]; }
    red[tid] = sum; __syncthreads();
    for (int off = 128; off > 0; off >>= 1) {
        if (tid < off) red[tid] += red[tid + off];
        __syncthreads();
    }
    const float inv = 1.0f / red[0];
    __syncthreads();

    // stash this block's 64 weights; sp==0 also writes the weights output
#pragma unroll
    for (int j = 0; j < 8; j++) {
        const int s = tid + j * 256;
        const float w = local[j] * inv;
        if (s >= s0 && s < s0 + 64) ws[s - s0] = w;
        if (sp == 0) out[BB * HH + b * SS + s] = w;
    }
    __syncthreads();

    // ---- context partial over 64 s-rows, 2 independent chains ----
    float4 acc0 = make_float4(0.f, 0.f, 0.f, 0.f);
    float4 acc1 = make_float4(0.f, 0.f, 0.f, 0.f);
    const __half2* kp = (const __half2*)(g_k16 + ((size_t)s0 * BB + b) * HH) + tid * 2;
    const size_t sstr = (size_t)BB * (HH / 2);
#pragma unroll 8
    for (int s = 0; s < 64; s += 2) {
        const float w0 = ws[s], w1 = ws[s + 1];
        const __half2 a01 = kp[(size_t)s * sstr];
        const __half2 a23 = kp[(size_t)s * sstr + 1];
        const __half2 b01 = kp[(size_t)(s + 1) * sstr];
        const __half2 b23 = kp[(size_t)(s + 1) * sstr + 1];
        const float2 fa01 = __half22float2(a01), fa23 = __half22float2(a23);
        const float2 fb01 = __half22float2(b01), fb23 = __half22float2(b23);
        acc0.x += w0 * fa01.x; acc0.y += w0 * fa01.y;
        acc0.z += w0 * fa23.x; acc0.w += w0 * fa23.y;
        acc1.x += w1 * fb01.x; acc1.y += w1 * fb01.y;
        acc1.z += w1 * fb23.x; acc1.w += w1 * fb23.y;
    }
    float4 acc;
    acc.x = acc0.x + acc1.x; acc.y = acc0.y + acc1.y;
    acc.z = acc0.z + acc1.z; acc.w = acc0.w + acc1.w;
    ((float4*)g_ctx_part)[((size_t)sp * BB + b) * 256 + tid] = acc;
}

// ---------------------------------------------------------------------------
// ctx reduce: grid (128, 256). Each output float4 is summed by 4 threads
// (8 sp-chunks each), combined via smem with fixed association (deterministic).
// ---------------------------------------------------------------------------
__global__ void ctx_reduce_kernel(float* __restrict__ out) {
    __shared__ float4 part[256];
    const int g = blockIdx.x * 256 + threadIdx.x;   // [0, 32768)
    const int o = g >> 2;                           // output float4 index
    const int q = g & 3;                            // sp-quarter
    float4 acc = make_float4(0.f, 0.f, 0.f, 0.f);
#pragma unroll
    for (int i = 0; i < 8; i++) {
        const float4 v = ((const float4*)g_ctx_part)[(size_t)(q * 8 + i) * 8192 + o];
        acc.x += v.x; acc.y += v.y; acc.z += v.z; acc.w += v.w;
    }
    part[threadIdx.x] = acc;
    __syncthreads();
    if (q == 0) {
        const float4 a = part[threadIdx.x],     b = part[threadIdx.x + 1];
        const float4 c = part[threadIdx.x + 2], d = part[threadIdx.x + 3];
        float4 r;
        r.x = (a.x + b.x) + (c.x + d.x);
        r.y = (a.y + b.y) + (c.y + d.y);
        r.z = (a.z + b.z) + (c.z + d.z);
        r.w = (a.w + b.w) + (c.w + d.w);
        ((float4*)out)[o] = r;
    }
}

// ---------------------------------------------------------------------------
extern "C" void kernel_launch(void* const* d_in, const int* in_sizes, int n_in,
                              void* d_out, int out_size) {
    (void)in_sizes; (void)n_in; (void)out_size;
    const float* query = (const float*)d_in[0];
    const float* key   = (const float*)d_in[1];
    const float* Wa_w  = (const float*)d_in[2];
    const float* Wa_b  = (const float*)d_in[3];
    const float* Ua_w  = (const float*)d_in[4];
    const float* Ua_b  = (const float*)d_in[5];
    const float* va_w  = (const float*)d_in[6];
    float* out = (float*)d_out;  // [context (B*H) | weights (B*S)]

    cudaFuncSetAttribute(scores_kernel, cudaFuncAttributeMaxDynamicSharedMemorySize, SM_TOT);

    prep_kernel<<<1152 + 65536, 256>>>((const float4*)key, Ua_w, query, Wa_w, Wa_b, Ua_b);
    scores_kernel<<<dim3(4, SS / BM, BB), 256, SM_TOT>>>(va_w);
    context_part_kernel<<<dim3(BB, 32), 256>>>(out);
    ctx_reduce_kernel<<<128, 256>>>(out);
}